// round 1
// baseline (speedup 1.0000x reference)
#include <cuda_runtime.h>
#include <math_constants.h>

// Problem constants
#define BATCH 64
#define LSEQ  900
#define DHEAD 64
#define TQ    32          // query rows per CTA
#define TK    64          // key/value rows per chunk
#define SPITCH 960        // padded score row length (15 * 64), multiple of 32
#define NCHUNK 15         // ceil(900/64) -> covers columns [0, 960)
#define NTHREADS 256

// Shared memory layout (floats):
//   S  : TQ * SPITCH              = 30720   (score slab, full 32 rows x 960 cols)
//   Qs : DHEAD * 34 (transposed)  =  2176   (pitch 34 keeps float2 loads 8B-aligned)
//   Ks : DHEAD * 68 (transposed)  =  4352   (pitch 68 keeps float4 loads 16B-aligned)
//        (Ks region is reused as Vs[64][64] natural layout in phase C)
#define SMEM_FLOATS (TQ * SPITCH + DHEAD * 34 + DHEAD * 68)

__global__ __launch_bounds__(NTHREADS, 1)
void sdpa_fused_kernel(const float* __restrict__ Q,
                       const float* __restrict__ K,
                       const float* __restrict__ V,
                       const int*   __restrict__ dur,
                       float* __restrict__ out,
                       float* __restrict__ score)
{
    extern __shared__ float sm[];
    float* S  = sm;                       // [TQ][SPITCH]
    float* Qs = sm + TQ * SPITCH;         // [DHEAD][34] transposed: Qs[d*34 + qi]
    float* Ks = Qs + DHEAD * 34;          // [DHEAD][68] transposed: Ks[d*68 + kj]

    const int tid = threadIdx.x;
    const int b   = blockIdx.y;
    const int q0  = blockIdx.x * TQ;
    const int durb = dur[b];

    const float* qb = Q + (size_t)b * LSEQ * DHEAD;
    const float* kb = K + (size_t)b * LSEQ * DHEAD;
    const float* vb = V + (size_t)b * LSEQ * DHEAD;

    // ---- Phase A: load Q tile, transposed into SMEM ------------------------
    for (int e = tid; e < TQ * DHEAD; e += NTHREADS) {
        int qi = e >> 6;          // 0..31
        int d  = e & 63;
        int r  = q0 + qi;
        Qs[d * 34 + qi] = (r < LSEQ) ? qb[(size_t)r * DHEAD + d] : 0.0f;
    }

    const int qg = tid >> 4;      // 0..15 -> query rows {2qg, 2qg+1}
    const int kg = tid & 15;      // 0..15 -> key cols  {4kg .. 4kg+3}

    // ---- Phase B: S = (Q K^T)/8 with ragged mask, full 960-wide slab -------
    for (int ck = 0; ck < NCHUNK; ck++) {
        const int c0 = ck * TK;

        __syncthreads();   // protect Ks against readers of previous chunk
        for (int e = tid; e < TK * DHEAD; e += NTHREADS) {
            int kj = e >> 6;
            int d  = e & 63;
            int c  = c0 + kj;
            Ks[d * 68 + kj] = (c < LSEQ) ? kb[(size_t)c * DHEAD + d] : 0.0f;
        }
        __syncthreads();

        float acc[2][4] = {{0.f,0.f,0.f,0.f},{0.f,0.f,0.f,0.f}};
        #pragma unroll 16
        for (int d = 0; d < DHEAD; d++) {
            float2 qv = *(const float2*)&Qs[d * 34 + 2 * qg];
            float4 kv = *(const float4*)&Ks[d * 68 + 4 * kg];
            acc[0][0] += qv.x * kv.x;  acc[0][1] += qv.x * kv.y;
            acc[0][2] += qv.x * kv.z;  acc[0][3] += qv.x * kv.w;
            acc[1][0] += qv.y * kv.x;  acc[1][1] += qv.y * kv.y;
            acc[1][2] += qv.y * kv.z;  acc[1][3] += qv.y * kv.w;
        }

        const float scl = 0.125f;       // 1/sqrt(64)
        const int cbase = c0 + 4 * kg;
        #pragma unroll
        for (int i = 0; i < 2; i++) {
            const int qi = 2 * qg + i;
            const int r  = q0 + qi;
            const bool rv = (r < durb);
            float4 sv;
            float* svp = (float*)&sv;
            #pragma unroll
            for (int j = 0; j < 4; j++) {
                const int c = cbase + j;
                float s;
                if (c >= LSEQ)            s = -CUDART_INF_F;   // pad cols: prob 0
                else if (rv && c < durb)  s = acc[i][j] * scl; // valid
                else                      s = -1e-12f;         // faithful mask fill
                svp[j] = s;
            }
            *(float4*)&S[qi * SPITCH + cbase] = sv;
        }
    }
    __syncthreads();

    // ---- Softmax per row (in place) + write normalized score to gmem -------
    {
        const int warp = tid >> 5;
        const int lane = tid & 31;
        for (int qi = warp; qi < TQ; qi += 8) {
            float* row = &S[qi * SPITCH];
            float m = -CUDART_INF_F;
            #pragma unroll 6
            for (int c = lane; c < SPITCH; c += 32) m = fmaxf(m, row[c]);
            #pragma unroll
            for (int o = 16; o; o >>= 1) m = fmaxf(m, __shfl_xor_sync(0xffffffffu, m, o));

            float ssum = 0.0f;
            #pragma unroll 6
            for (int c = lane; c < SPITCH; c += 32) {
                float e = __expf(row[c] - m);
                row[c] = e;
                ssum += e;
            }
            #pragma unroll
            for (int o = 16; o; o >>= 1) ssum += __shfl_xor_sync(0xffffffffu, ssum, o);
            const float inv = 1.0f / ssum;

            const int r = q0 + qi;
            if (r < LSEQ) {
                float* srow = score + ((size_t)b * LSEQ + r) * LSEQ;
                #pragma unroll 6
                for (int c = lane; c < SPITCH; c += 32) {
                    float p = row[c] * inv;
                    row[c] = p;
                    if (c < LSEQ) srow[c] = p;
                }
            } else {
                #pragma unroll 6
                for (int c = lane; c < SPITCH; c += 32) row[c] *= inv;
            }
        }
    }
    __syncthreads();

    // ---- Phase C: out = P @ V ---------------------------------------------
    {
        const int dg = kg;            // 0..15 -> out cols {4dg .. 4dg+3}
        float* Vs = Ks;               // reuse: natural layout Vs[cc*64 + d]
        float oacc[2][4] = {{0.f,0.f,0.f,0.f},{0.f,0.f,0.f,0.f}};

        for (int ck = 0; ck < NCHUNK; ck++) {
            const int c0 = ck * TK;
            __syncthreads();
            for (int e = tid; e < TK * DHEAD; e += NTHREADS) {
                int c = c0 + (e >> 6);
                Vs[e] = (c < LSEQ) ? vb[(size_t)c * DHEAD + (e & 63)] : 0.0f;
            }
            __syncthreads();

            #pragma unroll 8
            for (int cc = 0; cc < TK; cc++) {
                float p0 = S[(2 * qg    ) * SPITCH + c0 + cc];
                float p1 = S[(2 * qg + 1) * SPITCH + c0 + cc];
                float4 vv = *(const float4*)&Vs[cc * 64 + 4 * dg];
                oacc[0][0] += p0 * vv.x;  oacc[0][1] += p0 * vv.y;
                oacc[0][2] += p0 * vv.z;  oacc[0][3] += p0 * vv.w;
                oacc[1][0] += p1 * vv.x;  oacc[1][1] += p1 * vv.y;
                oacc[1][2] += p1 * vv.z;  oacc[1][3] += p1 * vv.w;
            }
        }

        #pragma unroll
        for (int i = 0; i < 2; i++) {
            const int r = q0 + 2 * qg + i;
            if (r < LSEQ) {
                float4 ov = make_float4(oacc[i][0], oacc[i][1], oacc[i][2], oacc[i][3]);
                *(float4*)&out[((size_t)b * LSEQ + r) * DHEAD + 4 * dg] = ov;
            }
        }
    }
}

extern "C" void kernel_launch(void* const* d_in, const int* in_sizes, int n_in,
                              void* d_out, int out_size)
{
    (void)in_sizes; (void)n_in; (void)out_size;
    const float* Q   = (const float*)d_in[0];
    const float* K   = (const float*)d_in[1];
    const float* V   = (const float*)d_in[2];
    const int*   dur = (const int*)d_in[3];

    float* out   = (float*)d_out;
    float* score = out + (size_t)BATCH * LSEQ * DHEAD;   // tuple order: (out, score)

    const int smem_bytes = SMEM_FLOATS * (int)sizeof(float);   // 148992 B
    cudaFuncSetAttribute(sdpa_fused_kernel,
                         cudaFuncAttributeMaxDynamicSharedMemorySize, smem_bytes);

    dim3 grid((LSEQ + TQ - 1) / TQ, BATCH);   // (29, 64)
    sdpa_fused_kernel<<<grid, NTHREADS, smem_bytes>>>(Q, K, V, dur, out, score);
}

// round 3
// speedup vs baseline: 2.9755x; 2.9755x over previous
#include <cuda_runtime.h>
#include <math_constants.h>

#define BATCH 64
#define LSEQ  900
#define DHEAD 64
#define TQ    32          // query rows per CTA
#define TK    128         // key/value cols per chunk
#define SPITCH 960        // padded score row pitch
#define NTHREADS 512

// Per-batch V column sums (device-global scratch; no allocation).
__device__ __align__(16) float g_full[BATCH * DHEAD];
__device__ __align__(16) float g_tail[BATCH * DHEAD];

// ---------------- kernel 1: per-batch full & tail V sums ----------------
__global__ void vsum_kernel(const float* __restrict__ V, const int* __restrict__ dur)
{
    __shared__ float sf[4][64];
    __shared__ float st_[4][64];
    const int b   = blockIdx.x;
    const int d   = threadIdx.x & 63;
    const int seg = threadIdx.x >> 6;           // 0..3
    const int durb = dur[b];
    const float* vb = V + (size_t)b * LSEQ * DHEAD;
    const int c0 = seg * 225, c1 = c0 + 225;
    float full = 0.f, tail = 0.f;
    for (int c = c0; c < c1; c++) {
        float v = vb[(size_t)c * DHEAD + d];
        full += v;
        if (c >= durb) tail += v;
    }
    sf[seg][d] = full;  st_[seg][d] = tail;
    __syncthreads();
    if (seg == 0) {
        g_full[b * 64 + d] = sf[0][d] + sf[1][d] + sf[2][d] + sf[3][d];
        g_tail[b * 64 + d] = st_[0][d] + st_[1][d] + st_[2][d] + st_[3][d];
    }
}

// ---------------- kernel 2: fused masked attention ----------------------
// SMEM floats: S 30720 | Qs 2176 (pitch 34, transposed) | Ks 8192 (swizzled) | pm 32 | uf 32
#define SMEM_FLOATS (TQ * SPITCH + 2176 + 8192 + 64)

__global__ __launch_bounds__(NTHREADS, 1)
void sdpa_fused_kernel(const float* __restrict__ Q,
                       const float* __restrict__ K,
                       const float* __restrict__ V,
                       const int*   __restrict__ dur,
                       float* __restrict__ out,
                       float* __restrict__ score)
{
    extern __shared__ float sm[];
    float* S   = sm;                       // [TQ][SPITCH]
    float* Qs  = sm + TQ * SPITCH;         // transposed Q: Qs[d*34 + qi]
    float* Ks  = Qs + 2176;                // swizzled transposed K / natural V
    float* pmv = Ks + 8192;                // per-row masked prob
    float* ufv = pmv + 32;                 // per-row uniform flag value

    const int tid  = threadIdx.x;
    const int b    = blockIdx.y;
    const int q0   = blockIdx.x * TQ;
    const int durb = dur[b];
    const int warp = tid >> 5;
    const int lane = tid & 31;
    const float inv900 = 1.0f / 900.0f;

    // ---- fast path: whole tile fully masked -> uniform rows --------------
    if (q0 >= durb) {
        for (int qi = warp; qi < TQ; qi += 16) {
            int r = q0 + qi;
            if (r < LSEQ) {
                float* srow = score + ((size_t)b * LSEQ + r) * LSEQ;
                for (int c = lane; c < LSEQ; c += 32) __stcs(&srow[c], inv900);
            }
        }
        for (int e = tid; e < TQ * DHEAD; e += NTHREADS) {
            int qi = e >> 6, d = e & 63, r = q0 + qi;
            if (r < LSEQ)
                out[((size_t)b * LSEQ + r) * DHEAD + d] = g_full[b * 64 + d] * inv900;
        }
        return;
    }

    const int CP  = (durb + 63) & ~63;         // padded valid-col count (<=960)
    const int nch = (CP + TK - 1) / TK;

    const float* qb = Q + (size_t)b * LSEQ * DHEAD;
    const float* kb = K + (size_t)b * LSEQ * DHEAD;
    const float* vb = V + (size_t)b * LSEQ * DHEAD;

    // ---- Phase A: Q tile transposed into SMEM ----------------------------
    for (int e = tid; e < TQ * DHEAD; e += NTHREADS) {
        int qi = e >> 6, d = e & 63, r = q0 + qi;
        Qs[d * 34 + qi] = (r < durb) ? qb[(size_t)r * DHEAD + d] : 0.0f;
    }

    const int qg = warp;          // 0..15 -> rows {2qg, 2qg+1}
    const int kg = lane;          // 0..31 -> cols {4kg..4kg+3} within chunk

    // ---- Phase B: S = (Q K^T)/8 over valid columns only ------------------
    for (int ck = 0; ck < nch; ck++) {
        const int c0 = ck * TK;
        __syncthreads();
        // K chunk -> swizzled transposed SMEM (conflict-free STS & LDS.128)
        for (int e = tid; e < TK * DHEAD; e += NTHREADS) {
            int dlo = e & 7;
            int klo = (e >> 3) & 15;
            int khi = (e >> 7) & 7;
            int dhi = (e >> 10) & 7;
            int kj  = (khi << 4) | klo;
            int d   = (dhi << 3) | dlo;
            int c   = c0 + kj;
            float v = (c < durb) ? kb[(size_t)c * DHEAD + d] : 0.0f;
            int g   = (kj >> 2) ^ (d & 31);
            Ks[d * 128 + (g << 2) + (kj & 3)] = v;
        }
        __syncthreads();

        float acc[2][4] = {{0.f,0.f,0.f,0.f},{0.f,0.f,0.f,0.f}};
        #pragma unroll 8
        for (int d = 0; d < DHEAD; d++) {
            float2 qv = *(const float2*)&Qs[d * 34 + 2 * qg];
            float4 kv = *(const float4*)&Ks[d * 128 + ((kg ^ (d & 31)) << 2)];
            acc[0][0] += qv.x * kv.x;  acc[0][1] += qv.x * kv.y;
            acc[0][2] += qv.x * kv.z;  acc[0][3] += qv.x * kv.w;
            acc[1][0] += qv.y * kv.x;  acc[1][1] += qv.y * kv.y;
            acc[1][2] += qv.y * kv.z;  acc[1][3] += qv.y * kv.w;
        }

        const int cbase = c0 + 4 * kg;
        if (cbase < CP) {
            const float scl = 0.125f;
            #pragma unroll
            for (int i = 0; i < 2; i++) {
                int qi = 2 * qg + i;
                float4 sv;
                float* svp = (float*)&sv;
                #pragma unroll
                for (int j = 0; j < 4; j++) {
                    int c = cbase + j;
                    svp[j] = (c < durb) ? acc[i][j] * scl : -CUDART_INF_F;
                }
                *(float4*)&S[qi * SPITCH + cbase] = sv;
            }
        }
    }
    __syncthreads();

    // ---- Softmax per row + analytic masked tail + score write ------------
    for (int qi = warp; qi < TQ; qi += 16) {
        const int r = q0 + qi;
        float* row = &S[qi * SPITCH];
        if (r < durb) {
            float m = -CUDART_INF_F;
            for (int c = lane; c < CP; c += 32) m = fmaxf(m, row[c]);
            #pragma unroll
            for (int o = 16; o; o >>= 1) m = fmaxf(m, __shfl_xor_sync(0xffffffffu, m, o));
            if (durb < LSEQ) m = fmaxf(m, -1e-12f);

            float ssum = 0.0f;
            for (int c = lane; c < CP; c += 32) {
                float e = __expf(row[c] - m);   // exp(-inf)=0 on pad cols
                row[c] = e;
                ssum += e;
            }
            #pragma unroll
            for (int o = 16; o; o >>= 1) ssum += __shfl_xor_sync(0xffffffffu, ssum, o);

            float e_mask = (durb < LSEQ) ? __expf(-1e-12f - m) : 0.0f;
            float Z   = ssum + (float)(LSEQ - durb) * e_mask;
            float inv = 1.0f / Z;
            float pmask = e_mask * inv;
            if (lane == 0) { pmv[qi] = pmask; ufv[qi] = 0.0f; }

            float* srow = score + ((size_t)b * LSEQ + r) * LSEQ;
            for (int c = lane; c < LSEQ; c += 32) {
                float p;
                if (c < durb) { p = row[c] * inv; row[c] = p; }
                else            p = pmask;
                __stcs(&srow[c], p);
            }
        } else {
            // fully-masked row inside a partially-valid tile
            for (int c = lane; c < CP; c += 32) row[c] = 0.0f;
            if (lane == 0) { pmv[qi] = 0.0f; ufv[qi] = inv900; }
            if (r < LSEQ) {
                float* srow = score + ((size_t)b * LSEQ + r) * LSEQ;
                for (int c = lane; c < LSEQ; c += 32) __stcs(&srow[c], inv900);
            }
        }
    }
    __syncthreads();

    // ---- Phase C: out = P(valid) @ V + pmask*Tail + uniform*Full ---------
    {
        const int t8  = tid & 255;
        const int rep = tid >> 8;            // split-K over cc parity
        const int qg2 = t8 >> 4;             // 0..15 -> rows {2qg2, 2qg2+1}
        const int dg  = t8 & 15;             // 0..15 -> out cols {4dg..4dg+3}
        float* Vs = Ks;                      // reuse: natural layout [cc][64]
        float oacc[2][4] = {{0.f,0.f,0.f,0.f},{0.f,0.f,0.f,0.f}};

        for (int ck = 0; ck < nch; ck++) {
            const int c0 = ck * TK;
            __syncthreads();
            for (int e = tid; e < TK * DHEAD; e += NTHREADS) {
                int cc = e >> 6, d = e & 63, c = c0 + cc;
                Vs[e] = (c < durb) ? vb[(size_t)c * DHEAD + d] : 0.0f;
            }
            __syncthreads();

            const int clen = min(TK, CP - c0);
            #pragma unroll 4
            for (int cc = rep; cc < clen; cc += 2) {
                float p0 = S[(2 * qg2    ) * SPITCH + c0 + cc];
                float p1 = S[(2 * qg2 + 1) * SPITCH + c0 + cc];
                float4 vv = *(const float4*)&Vs[cc * 64 + 4 * dg];
                oacc[0][0] += p0 * vv.x;  oacc[0][1] += p0 * vv.y;
                oacc[0][2] += p0 * vv.z;  oacc[0][3] += p0 * vv.w;
                oacc[1][0] += p1 * vv.x;  oacc[1][1] += p1 * vv.y;
                oacc[1][2] += p1 * vv.z;  oacc[1][3] += p1 * vv.w;
            }
        }
        __syncthreads();

        float* red = Qs;                     // reuse Qs region as reduction buf
        if (rep == 1) {
            float4* rb = (float4*)&red[t8 * 8];
            rb[0] = make_float4(oacc[0][0], oacc[0][1], oacc[0][2], oacc[0][3]);
            rb[1] = make_float4(oacc[1][0], oacc[1][1], oacc[1][2], oacc[1][3]);
        }
        __syncthreads();
        if (rep == 0) {
            float4 r0 = ((float4*)&red[t8 * 8])[0];
            float4 r1 = ((float4*)&red[t8 * 8])[1];
            float4 tl = *(const float4*)&g_tail[b * 64 + 4 * dg];
            float4 fl = *(const float4*)&g_full[b * 64 + 4 * dg];
            #pragma unroll
            for (int i = 0; i < 2; i++) {
                int qi = 2 * qg2 + i;
                int r  = q0 + qi;
                if (r < LSEQ) {
                    float pm = pmv[qi], uf = ufv[qi];
                    float4 rr = i ? r1 : r0;
                    float4 ov;
                    ov.x = oacc[i][0] + rr.x + pm * tl.x + uf * fl.x;
                    ov.y = oacc[i][1] + rr.y + pm * tl.y + uf * fl.y;
                    ov.z = oacc[i][2] + rr.z + pm * tl.z + uf * fl.z;
                    ov.w = oacc[i][3] + rr.w + pm * tl.w + uf * fl.w;
                    *(float4*)&out[((size_t)b * LSEQ + r) * DHEAD + 4 * dg] = ov;
                }
            }
        }
    }
}

extern "C" void kernel_launch(void* const* d_in, const int* in_sizes, int n_in,
                              void* d_out, int out_size)
{
    (void)in_sizes; (void)n_in; (void)out_size;
    const float* Q   = (const float*)d_in[0];
    const float* K   = (const float*)d_in[1];
    const float* V   = (const float*)d_in[2];
    const int*   dur = (const int*)d_in[3];

    float* out   = (float*)d_out;
    float* score = out + (size_t)BATCH * LSEQ * DHEAD;   // tuple order: (out, score)

    vsum_kernel<<<BATCH, 256>>>(V, dur);

    const int smem_bytes = SMEM_FLOATS * (int)sizeof(float);   // 164,608 B
    cudaFuncSetAttribute(sdpa_fused_kernel,
                         cudaFuncAttributeMaxDynamicSharedMemorySize, smem_bytes);
    dim3 grid((LSEQ + TQ - 1) / TQ, BATCH);   // (29, 64)
    sdpa_fused_kernel<<<grid, NTHREADS, smem_bytes>>>(Q, K, V, dur, out, score);
}

// round 7
// speedup vs baseline: 4.3875x; 1.4745x over previous
#include <cuda_runtime.h>
#include <math_constants.h>
#include <cstdint>

#define BATCH 64
#define LSEQ  900
#define DHEAD 64
#define TQ    32          // query rows per CTA
#define TKB   256         // key/value cols per chunk (phase B & C)
#define SPITCH 960        // padded score row pitch
#define QPITCH 36
#define NTHREADS 512

// Per-batch V column sums (device-global scratch; no allocation).
__device__ __align__(16) float g_full[BATCH * DHEAD];
__device__ __align__(16) float g_tail[BATCH * DHEAD];

__device__ __forceinline__ void cp_async16(uint32_t dsm, const void* src, int szbytes) {
    asm volatile("cp.async.cg.shared.global [%0], [%1], 16, %2;\n"
                 :: "r"(dsm), "l"(src), "r"(szbytes));
}

// ---------------- kernel 1: per-batch full & tail V sums ----------------
__global__ void vsum_kernel(const float* __restrict__ V, const int* __restrict__ dur)
{
    __shared__ float sf[4][64];
    __shared__ float st_[4][64];
    const int b   = blockIdx.x;
    const int d   = threadIdx.x & 63;
    const int seg = threadIdx.x >> 6;
    const int durb = dur[b];
    const float* vb = V + (size_t)b * LSEQ * DHEAD;
    const int c0 = seg * 225, c1 = c0 + 225;
    float full = 0.f, tail = 0.f;
    for (int c = c0; c < c1; c++) {
        float v = vb[(size_t)c * DHEAD + d];
        full += v;
        if (c >= durb) tail += v;
    }
    sf[seg][d] = full;  st_[seg][d] = tail;
    __syncthreads();
    if (seg == 0) {
        g_full[b * 64 + d] = sf[0][d] + sf[1][d] + sf[2][d] + sf[3][d];
        g_tail[b * 64 + d] = st_[0][d] + st_[1][d] + st_[2][d] + st_[3][d];
    }
}

// ---------------- kernel 2: fused masked attention ----------------------
// SMEM floats: S 30720 | Qs 2304 | Ks 16384 (swizzled K / natural V / red) | pm 32 | uf 32
#define SMEM_FLOATS (TQ * SPITCH + 2304 + 16384 + 64)

__global__ __launch_bounds__(NTHREADS, 1)
void sdpa_fused_kernel(const float* __restrict__ Q,
                       const float* __restrict__ K,
                       const float* __restrict__ V,
                       const int*   __restrict__ dur,
                       float* __restrict__ out,
                       float* __restrict__ score)
{
    extern __shared__ float sm[];
    float* S   = sm;                       // [TQ][SPITCH]
    float* Qs  = sm + TQ * SPITCH;         // transposed Q: Qs[d*36 + qi]
    float* Ks  = Qs + 2304;                // swizzled transposed K / natural V / reduction
    float* pmv = Ks + 16384;               // per-row masked prob
    float* ufv = pmv + 32;                 // per-row uniform value

    const int tid  = threadIdx.x;
    const int b    = blockIdx.y;
    const int q0   = blockIdx.x * TQ;
    const int durb = dur[b];
    const int warp = tid >> 5;
    const int lane = tid & 31;
    const float inv900 = 1.0f / 900.0f;

    // ---- fast path: whole tile fully masked -> uniform rows --------------
    if (q0 >= durb) {
        const float4 u4 = make_float4(inv900, inv900, inv900, inv900);
        for (int qi = warp; qi < TQ; qi += 16) {
            int r = q0 + qi;
            if (r < LSEQ) {
                float* srow = score + ((size_t)b * LSEQ + r) * LSEQ;
                for (int g = lane; g < 225; g += 32)
                    __stcs((float4*)&srow[4 * g], u4);
            }
        }
        for (int e = tid; e < TQ * DHEAD; e += NTHREADS) {
            int qi = e >> 6, d = e & 63, r = q0 + qi;
            if (r < LSEQ)
                out[((size_t)b * LSEQ + r) * DHEAD + d] = g_full[b * 64 + d] * inv900;
        }
        return;
    }

    const int CP  = (durb + 63) & ~63;         // padded valid-col count (<=960)
    const int nch = (CP + TKB - 1) / TKB;

    const float* qb = Q + (size_t)b * LSEQ * DHEAD;
    const float* kb = K + (size_t)b * LSEQ * DHEAD;
    const float* vb = V + (size_t)b * LSEQ * DHEAD;

    // ---- Phase A: Q tile transposed into SMEM ----------------------------
    for (int e = tid; e < TQ * DHEAD; e += NTHREADS) {
        int qi = e >> 6, d = e & 63, r = q0 + qi;
        Qs[d * QPITCH + qi] = (r < durb) ? qb[(size_t)r * DHEAD + d] : 0.0f;
    }

    const int qg = tid >> 6;      // 0..7  -> rows {4qg..4qg+3}
    const int cg = tid & 63;      // 0..63 -> cols {4cg..4cg+3} within chunk

    // ---- Phase B: S = (Q K^T)/8 over valid columns only ------------------
    for (int ck = 0; ck < nch; ck++) {
        const int c0    = ck * TKB;
        const int width = min(TKB, CP - c0);
        __syncthreads();
        // K chunk -> swizzled transposed SMEM
        #pragma unroll
        for (int it = 0; it < 8; it++) {
            int vidx = tid + NTHREADS * it;
            int kj = vidx >> 4;
            int d4 = (vidx & 15) << 2;
            if (kj < width) {
                int c = c0 + kj;
                float4 kv = make_float4(0.f, 0.f, 0.f, 0.f);
                if (c < durb) kv = *(const float4*)&kb[(size_t)c * DHEAD + d4];
                const float* kvp = (const float*)&kv;
                #pragma unroll
                for (int u = 0; u < 4; u++) {
                    int d = d4 + u;
                    int g = (kj >> 2) ^ ((d >> 2) & 15);
                    Ks[(d << 8) + (g << 2) + (kj & 3)] = kvp[u];
                }
            }
        }
        __syncthreads();

        if (4 * cg < width) {
            float acc[4][4];
            #pragma unroll
            for (int i = 0; i < 4; i++)
                #pragma unroll
                for (int j = 0; j < 4; j++) acc[i][j] = 0.f;

            const float* qp = Qs + 4 * qg;
            #pragma unroll 8
            for (int d = 0; d < DHEAD; d++) {
                float4 qv = *(const float4*)&qp[d * QPITCH];
                float4 kv = *(const float4*)&Ks[(d << 8) + ((cg ^ ((d >> 2) & 15)) << 2)];
                const float* qf = (const float*)&qv;
                #pragma unroll
                for (int i = 0; i < 4; i++) {
                    acc[i][0] += qf[i] * kv.x;  acc[i][1] += qf[i] * kv.y;
                    acc[i][2] += qf[i] * kv.z;  acc[i][3] += qf[i] * kv.w;
                }
            }

            const int cbase = c0 + 4 * cg;
            const float scl = 0.125f;
            #pragma unroll
            for (int i = 0; i < 4; i++) {
                float4 sv;
                float* svp = (float*)&sv;
                #pragma unroll
                for (int j = 0; j < 4; j++) {
                    int c = cbase + j;
                    svp[j] = (c < durb) ? acc[i][j] * scl : -CUDART_INF_F;
                }
                *(float4*)&S[(4 * qg + i) * SPITCH + cbase] = sv;
            }
        }
    }
    __syncthreads();

    // ---- Softmax per row (float4) + analytic masked tail + score write ---
    {
        const int NG = CP >> 2;          // float4 groups in valid region
        for (int qi = warp; qi < TQ; qi += 16) {
            const int r = q0 + qi;
            float* row = &S[qi * SPITCH];
            if (r < durb) {
                float m = -CUDART_INF_F;
                for (int g = lane; g < NG; g += 32) {
                    float4 v = *(const float4*)&row[4 * g];
                    m = fmaxf(m, fmaxf(fmaxf(v.x, v.y), fmaxf(v.z, v.w)));
                }
                #pragma unroll
                for (int o = 16; o; o >>= 1) m = fmaxf(m, __shfl_xor_sync(0xffffffffu, m, o));
                if (durb < LSEQ) m = fmaxf(m, -1e-12f);

                float ssum = 0.0f;
                for (int g = lane; g < NG; g += 32) {
                    float4 v = *(const float4*)&row[4 * g];
                    v.x = __expf(v.x - m);  v.y = __expf(v.y - m);
                    v.z = __expf(v.z - m);  v.w = __expf(v.w - m);
                    *(float4*)&row[4 * g] = v;
                    ssum += (v.x + v.y) + (v.z + v.w);
                }
                #pragma unroll
                for (int o = 16; o; o >>= 1) ssum += __shfl_xor_sync(0xffffffffu, ssum, o);

                float e_mask = (durb < LSEQ) ? __expf(-1e-12f - m) : 0.0f;
                float Z   = ssum + (float)(LSEQ - durb) * e_mask;
                float inv = 1.0f / Z;
                float pmask = e_mask * inv;
                if (lane == 0) { pmv[qi] = pmask; ufv[qi] = 0.0f; }

                float* srow = score + ((size_t)b * LSEQ + r) * LSEQ;
                for (int g = lane; g < 225; g += 32) {
                    int c = 4 * g;
                    float4 rv = *(const float4*)&row[c];   // garbage beyond CP, unused
                    float4 ov, wv;
                    float* rp = (float*)&rv; float* op = (float*)&ov; float* wp = (float*)&wv;
                    #pragma unroll
                    for (int u = 0; u < 4; u++) {
                        bool vld = (c + u) < durb;
                        float p = rp[u] * inv;
                        op[u] = vld ? p : pmask;
                        wp[u] = vld ? p : 0.0f;
                    }
                    if (c < CP) *(float4*)&row[c] = wv;
                    __stcs((float4*)&srow[c], ov);
                }
            } else {
                const float4 z4 = make_float4(0.f, 0.f, 0.f, 0.f);
                for (int g = lane; g < NG; g += 32) *(float4*)&row[4 * g] = z4;
                if (lane == 0) { pmv[qi] = 0.0f; ufv[qi] = inv900; }
                if (r < LSEQ) {
                    const float4 u4 = make_float4(inv900, inv900, inv900, inv900);
                    float* srow = score + ((size_t)b * LSEQ + r) * LSEQ;
                    for (int g = lane; g < 225; g += 32)
                        __stcs((float4*)&srow[4 * g], u4);
                }
            }
        }
    }
    __syncthreads();

    // ---- Phase C: out = P(valid) @ V + pmask*Tail + uniform*Full ---------
    {
        const int qg2 = tid >> 6;        // 0..7  -> rows {4qg2..4qg2+3}
        const int dg  = tid & 15;        // 0..15 -> out cols {4dg..4dg+3}
        const int rep = (tid >> 4) & 3;  // split-K x4
        float* Vs = Ks;                  // natural layout [cc][64]

        float acc[4][4];
        #pragma unroll
        for (int i = 0; i < 4; i++)
            #pragma unroll
            for (int j = 0; j < 4; j++) acc[i][j] = 0.f;

        for (int ck = 0; ck < nch; ck++) {
            const int c0   = ck * TKB;
            const int clen = min(TKB, CP - c0);
            __syncthreads();
            #pragma unroll
            for (int it = 0; it < 8; it++) {
                int vidx = tid + NTHREADS * it;
                int cc = vidx >> 4;
                int d4 = (vidx & 15) << 2;
                if (cc < clen) {
                    int c = c0 + cc;
                    uint32_t dsm = (uint32_t)__cvta_generic_to_shared(&Vs[cc * 64 + d4]);
                    const float* src = (c < durb) ? &vb[(size_t)c * DHEAD + d4] : vb;
                    cp_async16(dsm, src, (c < durb) ? 16 : 0);
                }
            }
            asm volatile("cp.async.commit_group;\n" ::: "memory");
            asm volatile("cp.async.wait_group 0;\n" ::: "memory");
            __syncthreads();

            const int ngr = clen >> 2;
            #pragma unroll 2
            for (int ccg = rep; ccg < ngr; ccg += 4) {
                const int cb = c0 + 4 * ccg;
                float4 p[4];
                #pragma unroll
                for (int i = 0; i < 4; i++)
                    p[i] = *(const float4*)&S[(4 * qg2 + i) * SPITCH + cb];
                #pragma unroll
                for (int u = 0; u < 4; u++) {
                    float4 vv = *(const float4*)&Vs[(4 * ccg + u) * 64 + 4 * dg];
                    #pragma unroll
                    for (int i = 0; i < 4; i++) {
                        float pu = ((const float*)&p[i])[u];
                        acc[i][0] += pu * vv.x;  acc[i][1] += pu * vv.y;
                        acc[i][2] += pu * vv.z;  acc[i][3] += pu * vv.w;
                    }
                }
            }
        }
        __syncthreads();

        // split-K reduction in SMEM (reuse Ks region), padded stride 20
        float* red = Ks;
        const int cell = (qg2 * 16 + dg) * 20;
        if (rep) {
            #pragma unroll
            for (int i = 0; i < 4; i++)
                *(float4*)&red[(rep - 1) * 2560 + cell + 4 * i] =
                    make_float4(acc[i][0], acc[i][1], acc[i][2], acc[i][3]);
        }
        __syncthreads();
        if (rep == 0) {
            #pragma unroll
            for (int s = 0; s < 3; s++)
                #pragma unroll
                for (int i = 0; i < 4; i++) {
                    float4 rv = *(const float4*)&red[s * 2560 + cell + 4 * i];
                    acc[i][0] += rv.x;  acc[i][1] += rv.y;
                    acc[i][2] += rv.z;  acc[i][3] += rv.w;
                }
            float4 tl = *(const float4*)&g_tail[b * 64 + 4 * dg];
            float4 fl = *(const float4*)&g_full[b * 64 + 4 * dg];
            #pragma unroll
            for (int i = 0; i < 4; i++) {
                int qi = 4 * qg2 + i;
                int r  = q0 + qi;
                if (r < LSEQ) {
                    float pm = pmv[qi], uf = ufv[qi];
                    float4 ov;
                    ov.x = acc[i][0] + pm * tl.x + uf * fl.x;
                    ov.y = acc[i][1] + pm * tl.y + uf * fl.y;
                    ov.z = acc[i][2] + pm * tl.z + uf * fl.z;
                    ov.w = acc[i][3] + pm * tl.w + uf * fl.w;
                    *(float4*)&out[((size_t)b * LSEQ + r) * DHEAD + 4 * dg] = ov;
                }
            }
        }
    }
}

extern "C" void kernel_launch(void* const* d_in, const int* in_sizes, int n_in,
                              void* d_out, int out_size)
{
    (void)in_sizes; (void)n_in; (void)out_size;
    const float* Q   = (const float*)d_in[0];
    const float* K   = (const float*)d_in[1];
    const float* V   = (const float*)d_in[2];
    const int*   dur = (const int*)d_in[3];

    float* out   = (float*)d_out;
    float* score = out + (size_t)BATCH * LSEQ * DHEAD;   // tuple order: (out, score)

    vsum_kernel<<<BATCH, 256>>>(V, dur);

    const int smem_bytes = SMEM_FLOATS * (int)sizeof(float);   // 197,888 B
    cudaFuncSetAttribute(sdpa_fused_kernel,
                         cudaFuncAttributeMaxDynamicSharedMemorySize, smem_bytes);
    dim3 grid((LSEQ + TQ - 1) / TQ, BATCH);   // (29, 64)
    sdpa_fused_kernel<<<grid, NTHREADS, smem_bytes>>>(Q, K, V, dur, out, score);
}